// round 13
// baseline (speedup 1.0000x reference)
#include <cuda_runtime.h>
#include <cstdint>

#define N_Q 4096
#define NTHREADS 1024
#define EVAL_PT_SCORE 0.05f
#define D2_THRESH 25.0f   // 5.0^2
#define NBR_CAP 6
#define OVF 255
#define HCAP 1536         // stripe slice capacity (expected ~640)
#define WCAP 1024
#define NBUCK 1024
#define NCELLS 4096       // full 64x64 grid of 8px cells
#define NCNT (NBUCK + NCELLS)   // 5120 fused counters in prep

// prep smem: bkey u64[4096] @0 (8-aligned) | cs int[NCNT+1] | ccu int[NCNT] | warpsum int[64]
#define PREP_SMEM (8 * N_Q + 4 * (NCNT + 1) + 4 * NCNT + 256)      // 73,988
// resolve smem: hrec uint4[HCAP] @0 | scs int[704] | hidx u16 | wl u16 | nbr u16 | lstat u8 | nbrcnt u8
#define RES_SMEM  (16 * HCAP + 4 * 704 + 2 * HCAP + 2 * WCAP + 2 * WCAP * NBR_CAP + HCAP + WCAP)

// -------- device scratch (per class) --------
__device__ uint4 g_rec[2][N_Q];                 // cell-ordered (keylo, keyhi, x, y)
__device__ unsigned short g_ridx[2][N_Q];       // original index per record
__device__ unsigned short g_rank[2][N_Q];       // rank among valid (desc key), by orig idx
__device__ int g_cellstart[2][NCELLS + 1];
__device__ int g_stat[2][N_Q];                  // 0=pending 1=retained 2=suppressed/invalid

__device__ __forceinline__ int warp_incl_scan(int v) {
    int lane = threadIdx.x & 31;
    #pragma unroll
    for (int o = 1; o < 32; o <<= 1) {
        int n = __shfl_up_sync(0xffffffffu, v, o);
        if (lane >= o) v += n;
    }
    return v;
}

__device__ __forceinline__ unsigned long long mk_key(float s, int i) {
    bool valid = (s >= EVAL_PT_SCORE);
    unsigned int fb = __float_as_uint(s);
    return valid
        ? ((((unsigned long long)fb) << 32) | (unsigned int)(N_Q - 1 - i))
        : (unsigned long long)(unsigned int)(N_Q - 1 - i);
}

// ---------------- K1: per-class prep (softmax + cell CSR + ranks) ----------------
__global__ void __launch_bounds__(NTHREADS, 1)
prep_kernel(const float* __restrict__ logits,
            const float* __restrict__ boxes,
            const float* __restrict__ ts,
            float* __restrict__ out) {
    const int cls = blockIdx.x;
    const int tid = threadIdx.x;
    const int lane = tid & 31;
    const int wid = tid >> 5;

    extern __shared__ unsigned char sm[];
    unsigned long long* bkey = (unsigned long long*)sm;   // [N_Q] (offset 0: 8-aligned)
    int* cs  = (int*)(bkey + N_Q);                        // [NCNT+1]
    int* ccu = cs + (NCNT + 1);                           // [NCNT]
    int* warpsum = ccu + NCNT;                            // [64]

    for (int c = tid; c < NCNT + 1; c += NTHREADS) cs[c] = 0;
    __syncthreads();

    const float tw = ts[0], th = ts[1];
    unsigned long long rkey[4];
    float rx[4], ry[4];
    int rb[4], rcell[4];
    {
        const float2* lg2 = (const float2*)(logits + 12 * tid);
        float2 L0 = lg2[0], L1 = lg2[1], L2 = lg2[2];
        float2 L3 = lg2[3], L4 = lg2[4], L5 = lg2[5];
        float lg[12] = {L0.x, L0.y, L1.x, L1.y, L2.x, L2.y,
                        L3.x, L3.y, L4.x, L4.y, L5.x, L5.y};
        const float4* bx4 = (const float4*)(boxes + 8 * tid);
        float4 B0 = bx4[0], B1 = bx4[1];
        float bx[8] = {B0.x, B0.y, B0.z, B0.w, B1.x, B1.y, B1.z, B1.w};
        #pragma unroll
        for (int k = 0; k < 4; k++) {
            int j = 4 * tid + k;
            float l0 = lg[3 * k], l1 = lg[3 * k + 1], l2 = lg[3 * k + 2];
            float m = fmaxf(l0, fmaxf(l1, l2));
            float e0 = __expf(l0 - m), e1 = __expf(l1 - m), e2 = __expf(l2 - m);
            float inv = __fdividef(1.0f, e0 + e1 + e2);
            float p0 = e0 * inv, p1 = e1 * inv, p2 = e2 * inv;
            float x = bx[2 * k] * tw;
            float y = bx[2 * k + 1] * th;
            float s = cls ? p1 : p0;
            bool valid = (s >= EVAL_PT_SCORE);
            rkey[k] = mk_key(s, j);
            rx[k] = x; ry[k] = y;
            g_stat[cls][j] = valid ? 0 : 2;
            rb[k] = min(NBUCK - 1, (int)(s * (float)NBUCK));
            if (valid) atomicAdd(&cs[rb[k]], 1);
            int cx = min(63, max(0, (int)(x * 0.125f)));
            int cy = min(63, max(0, (int)(y * 0.125f)));
            rcell[k] = cy * 64 + cx;
            atomicAdd(&cs[NBUCK + rcell[k]], 1);
            if (cls == 0) {
                out[5 * j + 0] = 1.0f - p2;
                out[5 * j + 1] = x;
                out[5 * j + 2] = y;
                out[5 * j + 3] = 0.0f;
            } else {
                out[5 * j + 4] = 0.0f;
            }
        }
    }
    __syncthreads();

    // ---- fused exclusive scan over 5120 counters (5/thread) ----
    {
        int i0 = 5 * tid;
        int v0 = cs[i0], v1 = cs[i0 + 1], v2 = cs[i0 + 2];
        int v3 = cs[i0 + 3], v4 = cs[i0 + 4];
        int l = v0 + v1 + v2 + v3 + v4;
        int il = warp_incl_scan(l);
        if (lane == 31) warpsum[wid] = il;
        __syncthreads();
        if (wid == 0) warpsum[lane] = warp_incl_scan(warpsum[lane]);
        __syncthreads();
        int base = il - l + (wid ? warpsum[wid - 1] : 0);
        cs[i0] = base;                      ccu[i0] = base;
        cs[i0 + 1] = base + v0;             ccu[i0 + 1] = base + v0;
        cs[i0 + 2] = base + v0 + v1;        ccu[i0 + 2] = base + v0 + v1;
        cs[i0 + 3] = base + v0 + v1 + v2;   ccu[i0 + 3] = base + v0 + v1 + v2;
        cs[i0 + 4] = base + l - v4;         ccu[i0 + 4] = base + l - v4;
        if (tid == NTHREADS - 1) cs[NCNT] = base + l;
    }
    __syncthreads();
    const int nv = cs[NBUCK];

    // ---- scatter: bucket keys (smem) + cell-ordered records (gmem) ----
    #pragma unroll
    for (int k = 0; k < 4; k++) {
        int j = 4 * tid + k;
        if (rkey[k] >> 32) {
            int bp = atomicAdd(&ccu[rb[k]], 1);
            bkey[bp] = rkey[k];
        }
        int pos = atomicAdd(&ccu[NBUCK + rcell[k]], 1) - nv;
        g_rec[cls][pos] = make_uint4((unsigned int)rkey[k],
                                     (unsigned int)(rkey[k] >> 32),
                                     __float_as_uint(rx[k]),
                                     __float_as_uint(ry[k]));
        g_ridx[cls][pos] = (unsigned short)j;
    }
    __syncthreads();

    // ---- precompute rank for every valid point ----
    #pragma unroll
    for (int k = 0; k < 4; k++) {
        if (!(rkey[k] >> 32)) continue;
        int b = rb[k];
        int r = nv - cs[b + 1];
        int e = cs[b + 1];
        for (int q = cs[b]; q < e; q++)
            if (bkey[q] > rkey[k]) r++;
        g_rank[cls][4 * tid + k] = (unsigned short)r;
    }

    // ---- publish cellstart ----
    for (int c = tid; c < NCELLS + 1; c += NTHREADS)
        g_cellstart[cls][c] = cs[NBUCK + c] - nv;
}

// ---------------- K2: stripe-local edge build + dataflow resolve ----------------
__global__ void __launch_bounds__(NTHREADS, 1)
resolve_kernel(float* __restrict__ out) {
    const int rs = blockIdx.x & 7;          // stripe 0..7 (8 cell-rows each)
    const int cls = blockIdx.x >> 3;
    const int tid = threadIdx.x;
    const int row0 = 8 * rs;
    const int gr0 = max(row0 - 1, 0);
    const int gr1 = min(row0 + 8, 63);
    const int ncl = (gr1 - gr0 + 1) * 64;   // local cells (<= 640)
    const int cbase = gr0 * 64;

    extern __shared__ unsigned char sm[];
    uint4* hrec = (uint4*)sm;                                  // [HCAP]
    int* scs = (int*)(hrec + HCAP);                            // [704]
    unsigned short* hidx = (unsigned short*)(scs + 704);       // [HCAP]
    unsigned short* wl   = hidx + HCAP;                        // [WCAP]
    unsigned short* nbr  = wl + WCAP;                          // [WCAP*NBR_CAP]
    unsigned char* lstat = (unsigned char*)(nbr + WCAP * NBR_CAP); // [HCAP]
    unsigned char* nbrcnt = lstat + HCAP;                      // [WCAP]
    volatile unsigned char* vls = (volatile unsigned char*)lstat;
    volatile int* vg = (volatile int*)g_stat[cls];
    __shared__ int s_wl;

    if (tid == 0) s_wl = 0;
    for (int c = tid; c <= ncl; c += NTHREADS)
        scs[c] = g_cellstart[cls][cbase + c];
    __syncthreads();
    const int pbase = scs[0];
    const int pcnt = scs[ncl] - pbase;

    // ---- load slice records (coalesced) ----
    for (int p = tid; p < pcnt; p += NTHREADS) {
        uint4 R = g_rec[cls][pbase + p];
        hrec[p] = R;
        hidx[p] = g_ridx[cls][pbase + p];
        lstat[p] = R.y ? (unsigned char)0 : (unsigned char)2;
    }
    __syncthreads();

    #define EMIT(idx, keyhi) \
        out[5 * (int)g_rank[cls][idx] + 3 + cls] = __uint_as_float(keyhi)

    #define PUBLISH(p, idx, cy, v) do {                                       \
        vls[p] = (unsigned char)(v);                                          \
        int m_ = (cy) & 7;                                                    \
        if ((m_ == 0 && rs > 0) || (m_ == 7 && rs < 7)) vg[idx] = (int)(v);   \
    } while (0)

    // ---- edge build for OWNED records (rows row0..row0+7, contiguous) ----
    const int ostart = scs[(row0 - gr0) * 64] - pbase;
    const int oend   = scs[(row0 + 8 - gr0) * 64] - pbase;
    for (int p = ostart + tid; p < oend; p += NTHREADS) {
        uint4 R = hrec[p];
        if (R.y == 0) continue;                    // invalid
        unsigned long long kj = ((unsigned long long)R.y << 32) | R.x;
        float xj = __uint_as_float(R.z), yj = __uint_as_float(R.w);
        int cx = min(63, max(0, (int)(xj * 0.125f)));
        int cy = min(63, max(0, (int)(yj * 0.125f)));
        int x0 = max(cx - 1, 0), x1 = min(cx + 1, 63);
        unsigned short tmp[NBR_CAP];
        int cnt = 0;
        #pragma unroll
        for (int d = -1; d <= 1; d++) {
            int gcy = cy + d;
            if (gcy < 0 || gcy > 63) continue;
            bool rem = (gcy < row0) || (gcy >= row0 + 8);
            int lrow = (gcy - gr0) * 64;
            int qs = scs[lrow + x0] - pbase;
            int qe = scs[lrow + x1 + 1] - pbase;
            for (int q = qs; q < qe; q++) {
                uint4 C = hrec[q];
                unsigned long long ki = ((unsigned long long)C.y << 32) | C.x;
                if (ki <= kj) continue;            // lower rank / invalid / self
                float dx = __uint_as_float(C.z) - xj;
                float dy = __uint_as_float(C.w) - yj;
                if (dx * dx + dy * dy < D2_THRESH) {
                    if (cnt < NBR_CAP)
                        tmp[cnt] = rem ? (unsigned short)(0x8000u | hidx[q])
                                       : (unsigned short)q;
                    cnt++;
                }
            }
        }
        int i = hidx[p];
        if (cnt == 0) {
            PUBLISH(p, i, cy, 1u);
            EMIT(i, R.y);
        } else {
            int w = atomicAdd(&s_wl, 1);
            wl[w] = (unsigned short)p;
            nbrcnt[w] = (cnt > NBR_CAP) ? (unsigned char)OVF : (unsigned char)cnt;
            #pragma unroll
            for (int k = 0; k < NBR_CAP; k++)
                if (k < cnt) nbr[w * NBR_CAP + k] = tmp[k];
        }
    }
    __syncthreads();
    const int nwl = s_wl;

    // ---- dataflow resolution: local via smem slice, cross-stripe via L2 ----
    for (int w = tid; w < nwl; w += NTHREADS) {
        int p = wl[w];
        int i = hidx[p];
        uint4 R = hrec[p];
        unsigned long long kj = ((unsigned long long)R.y << 32) | R.x;
        float xj = __uint_as_float(R.z), yj = __uint_as_float(R.w);
        int cy = min(63, max(0, (int)(yj * 0.125f)));
        int c = nbrcnt[w];
        unsigned int res = 0;
        if (c != OVF) {
            while (res == 0) {
                bool sup = false, pend = false;
                #pragma unroll 1
                for (int k = 0; k < c; k++) {
                    unsigned short nb = nbr[w * NBR_CAP + k];
                    int st = (nb & 0x8000) ? vg[nb & 0x7FFF] : (int)vls[nb];
                    if (st == 1) { sup = true; break; }
                    if (st == 0) pend = true;
                }
                if (sup) res = 2;
                else if (!pend) res = 1;
            }
        } else {
            int cx = min(63, max(0, (int)(xj * 0.125f)));
            int x0 = max(cx - 1, 0), x1 = min(cx + 1, 63);
            while (res == 0) {
                bool sup = false, pend = false;
                #pragma unroll 1
                for (int d = -1; d <= 1 && !sup; d++) {
                    int gcy = cy + d;
                    if (gcy < 0 || gcy > 63) continue;
                    bool rem = (gcy < row0) || (gcy >= row0 + 8);
                    int lrow = (gcy - gr0) * 64;
                    int qs = scs[lrow + x0] - pbase;
                    int qe = scs[lrow + x1 + 1] - pbase;
                    for (int q = qs; q < qe; q++) {
                        uint4 C = hrec[q];
                        unsigned long long ki = ((unsigned long long)C.y << 32) | C.x;
                        if (ki <= kj) continue;
                        float dx = __uint_as_float(C.z) - xj;
                        float dy = __uint_as_float(C.w) - yj;
                        if (dx * dx + dy * dy < D2_THRESH) {
                            int st = rem ? vg[hidx[q]] : (int)vls[q];
                            if (st == 1) { sup = true; break; }
                            if (st == 0) pend = true;
                        }
                    }
                }
                if (sup) res = 2;
                else if (!pend) res = 1;
            }
        }
        PUBLISH(p, i, cy, res);
        if (res == 1) EMIT(i, R.y);
    }
}

extern "C" void kernel_launch(void* const* d_in, const int* in_sizes, int n_in,
                              void* d_out, int out_size) {
    const float* logits = (const float*)d_in[0];   // [1,4096,3]
    const float* boxes  = (const float*)d_in[1];   // [1,4096,2]
    // d_in[2] = pred_gids (unused by reference)
    const float* ts     = (const float*)d_in[3];   // [1,2] = (w,h)
    float* out = (float*)d_out;                    // [1,4096,5]

    cudaFuncSetAttribute(prep_kernel,
                         cudaFuncAttributeMaxDynamicSharedMemorySize, PREP_SMEM);
    prep_kernel<<<2, NTHREADS, PREP_SMEM>>>(logits, boxes, ts, out);

    cudaFuncSetAttribute(resolve_kernel,
                         cudaFuncAttributeMaxDynamicSharedMemorySize, RES_SMEM);
    resolve_kernel<<<16, NTHREADS, RES_SMEM>>>(out);
}

// round 14
// speedup vs baseline: 1.8767x; 1.8767x over previous
#include <cuda_runtime.h>
#include <cstdint>

#define N_Q 4096
#define NTHREADS 1024
#define EVAL_PT_SCORE 0.05f
#define D2_THRESH 25.0f   // 5.0^2
#define NBR_CAP 6
#define OVF 255
#define HCAP 1536         // stripe slice capacity (expected ~640)
#define WCAP 1024
#define NBUCK 1024
#define NCELL 640         // 10 rows * 64 cols
#define NCNT (NBUCK + NCELL)   // 1664 fused counters

// resolve smem: hrec uint4[HCAP] @0 | bkey u64[N_Q] | cs int[NCNT+1] | ccu int[NCNT]
//               warpsum int[64] | hidx u16[HCAP] | wl u16[WCAP] | nbr u16[WCAP*6]
//               lstat u8[HCAP] | nbrcnt u8[WCAP]  => 90,884 bytes
#define RES_SMEM (16 * HCAP + 8 * N_Q + 4 * (NCNT + 1) + 4 * NCNT + 256 \
                  + 2 * HCAP + 2 * WCAP + 2 * WCAP * NBR_CAP + HCAP + WCAP)

// -------- device scratch (per class) --------
__device__ uint4 g_pt[2][N_Q];    // (keylo, keyhi, x, y) by original index
__device__ int g_stat[2][N_Q];    // 0=pending 1=retained 2=suppressed/invalid

__device__ __forceinline__ int warp_incl_scan(int v) {
    int lane = threadIdx.x & 31;
    #pragma unroll
    for (int o = 1; o < 32; o <<= 1) {
        int n = __shfl_up_sync(0xffffffffu, v, o);
        if (lane >= o) v += n;
    }
    return v;
}

__device__ __forceinline__ unsigned long long mk_key(float s, int i) {
    bool valid = (s >= EVAL_PT_SCORE);
    unsigned int fb = __float_as_uint(s);
    return valid
        ? ((((unsigned long long)fb) << 32) | (unsigned int)(N_Q - 1 - i))
        : (unsigned long long)(unsigned int)(N_Q - 1 - i);
}

// ---------------- K1: per-point prep (1 pt/thread, 8 CTAs) ----------------
__global__ void __launch_bounds__(NTHREADS)
prep_kernel(const float* __restrict__ logits,
            const float* __restrict__ boxes,
            const float* __restrict__ ts,
            float* __restrict__ out) {
    int t = blockIdx.x * NTHREADS + threadIdx.x;   // 0..8191
    int cls = t >> 12;
    int j = t & (N_Q - 1);
    float l0 = logits[3 * j + 0];
    float l1 = logits[3 * j + 1];
    float l2 = logits[3 * j + 2];
    float m = fmaxf(l0, fmaxf(l1, l2));
    float e0 = __expf(l0 - m), e1 = __expf(l1 - m), e2 = __expf(l2 - m);
    float inv = __fdividef(1.0f, e0 + e1 + e2);
    float p0 = e0 * inv, p1 = e1 * inv, p2 = e2 * inv;
    float x = boxes[2 * j + 0] * ts[0];
    float y = boxes[2 * j + 1] * ts[1];
    float s = cls ? p1 : p0;
    unsigned long long key = mk_key(s, j);
    g_pt[cls][j] = make_uint4((unsigned int)key, (unsigned int)(key >> 32),
                              __float_as_uint(x), __float_as_uint(y));
    g_stat[cls][j] = (s >= EVAL_PT_SCORE) ? 0 : 2;
    if (cls == 0) {
        out[5 * j + 0] = 1.0f - p2;
        out[5 * j + 1] = x;
        out[5 * j + 2] = y;
        out[5 * j + 3] = 0.0f;
    } else {
        out[5 * j + 4] = 0.0f;
    }
}

// ---------------- K2: stripe CSR + edge build + gmem dataflow ----------------
__global__ void __launch_bounds__(NTHREADS, 1)
resolve_kernel(float* __restrict__ out) {
    const int rank = blockIdx.x & 7;        // stripe 0..7 (8 cell-rows each)
    const int cls = blockIdx.x >> 3;
    const int tid = threadIdx.x;
    const int lane = tid & 31;
    const int wid = tid >> 5;
    const int rbase = 8 * rank - 1;         // stripe-local row 0 = cell row rbase

    extern __shared__ unsigned char sm[];
    uint4* hrec = (uint4*)sm;                                      // [HCAP]
    unsigned long long* bkey = (unsigned long long*)(hrec + HCAP); // [N_Q]
    int* cs  = (int*)(bkey + N_Q);                                 // [NCNT+1]
    int* ccu = cs + (NCNT + 1);                                    // [NCNT]
    int* warpsum = ccu + NCNT;                                     // [64]
    unsigned short* hidx = (unsigned short*)(warpsum + 64);        // [HCAP]
    unsigned short* wl   = hidx + HCAP;                            // [WCAP]
    unsigned short* nbr  = wl + WCAP;                              // [WCAP*NBR_CAP]
    unsigned char* lstat = (unsigned char*)(nbr + WCAP * NBR_CAP); // [HCAP]
    unsigned char* nbrcnt = lstat + HCAP;                          // [WCAP]
    volatile unsigned char* vls = (volatile unsigned char*)lstat;
    volatile int* vg = (volatile int*)g_stat[cls];
    __shared__ int s_wl;

    // ---- zero counters ----
    for (int c = tid; c < NCNT + 1; c += NTHREADS) cs[c] = 0;
    if (tid == 0) s_wl = 0;
    __syncthreads();

    // ---- load packed records (coalesced LDG.128); histograms ----
    unsigned long long rkey[4];
    float rx[4], ry[4];
    int rb[4], rlc[4];
    #pragma unroll
    for (int k = 0; k < 4; k++) {
        int j = k * NTHREADS + tid;
        uint4 R = g_pt[cls][j];
        unsigned long long key = ((unsigned long long)R.y << 32) | R.x;
        float x = __uint_as_float(R.z), y = __uint_as_float(R.w);
        rkey[k] = key; rx[k] = x; ry[k] = y;
        if (R.y) {
            float s = __uint_as_float(R.y);
            rb[k] = min(NBUCK - 1, (int)(s * (float)NBUCK));
            atomicAdd(&cs[rb[k]], 1);
        } else rb[k] = 0;
        int cx = min(63, max(0, (int)(x * 0.125f)));
        int cy = min(63, max(0, (int)(y * 0.125f)));
        int lr = cy - rbase;
        rlc[k] = (lr >= 0 && lr < 10) ? (lr * 64 + cx) : -1;
        if (rlc[k] >= 0) atomicAdd(&cs[NBUCK + rlc[k]], 1);
    }
    __syncthreads();

    // ---- fused exclusive scan over 1664 counters (2/thread) ----
    {
        int i0 = 2 * tid, i1 = i0 + 1;
        int v0 = (i0 < NCNT) ? cs[i0] : 0;
        int v1 = (i1 < NCNT) ? cs[i1] : 0;
        int l = v0 + v1;
        int il = warp_incl_scan(l);
        if (lane == 31) warpsum[wid] = il;
        __syncthreads();
        if (wid == 0) warpsum[lane] = warp_incl_scan(warpsum[lane]);
        __syncthreads();
        int base = il - l + (wid ? warpsum[wid - 1] : 0);
        if (i0 < NCNT) { cs[i0] = base;       ccu[i0] = base; }
        if (i1 < NCNT) { cs[i1] = base + v0;  ccu[i1] = base + v0; }
        if (tid == 0) cs[NCNT] = warpsum[31];
    }
    __syncthreads();
    const int nv = cs[NBUCK];            // total valid points

    // ---- scatter: bucket-ordered keys + stripe records (lstat init inline) ----
    #pragma unroll
    for (int k = 0; k < 4; k++) {
        int j = k * NTHREADS + tid;
        if (rkey[k] >> 32) {
            int bp = atomicAdd(&ccu[rb[k]], 1);
            bkey[bp] = rkey[k];
        }
        if (rlc[k] >= 0) {
            int pos = atomicAdd(&ccu[NBUCK + rlc[k]], 1) - nv;
            hrec[pos] = make_uint4((unsigned int)rkey[k],
                                   (unsigned int)(rkey[k] >> 32),
                                   __float_as_uint(rx[k]),
                                   __float_as_uint(ry[k]));
            hidx[pos] = (unsigned short)j;
            lstat[pos] = (rkey[k] >> 32) ? (unsigned char)0 : (unsigned char)2;
        }
    }
    __syncthreads();

    #define EMIT(kj) do {                                                     \
        float sc_ = __uint_as_float((unsigned int)((kj) >> 32));              \
        int b_ = min(NBUCK - 1, (int)(sc_ * (float)NBUCK));                   \
        int rpos_ = nv - cs[b_ + 1];                                          \
        int qe_ = cs[b_ + 1];                                                 \
        for (int q_ = cs[b_]; q_ < qe_; q_++)                                 \
            if (bkey[q_] > (kj)) rpos_++;                                     \
        out[5 * rpos_ + 3 + cls] = sc_;                                       \
    } while (0)

    #define PUBLISH(p, idx, lr, v) do {                                       \
        vls[p] = (unsigned char)(v);                                          \
        if (((lr) == 1 && rank > 0) || ((lr) == 8 && rank < 7))               \
            vg[idx] = (int)(v);                                               \
    } while (0)

    // ---- edge build for OWNED records (local rows 1..8, contiguous) ----
    const int pstart = cs[NBUCK + 64] - nv;
    const int pend   = cs[NBUCK + 9 * 64] - nv;
    for (int p = pstart + tid; p < pend; p += NTHREADS) {
        uint4 R = hrec[p];
        if (R.y == 0) continue;                    // invalid
        unsigned long long kj = ((unsigned long long)R.y << 32) | R.x;
        float xj = __uint_as_float(R.z), yj = __uint_as_float(R.w);
        int cx = min(63, max(0, (int)(xj * 0.125f)));
        int cy = min(63, max(0, (int)(yj * 0.125f)));
        int lr = cy - rbase;                       // 1..8
        int x0 = max(cx - 1, 0), x1 = min(cx + 1, 63);
        unsigned short tmp[NBR_CAP];
        int cnt = 0;
        #pragma unroll
        for (int rr = lr - 1; rr <= lr + 1; rr++) {
            unsigned short rem = (rr == 0 || rr == 9) ? 0x8000 : 0;
            int qs = cs[NBUCK + rr * 64 + x0] - nv;
            int qe = cs[NBUCK + rr * 64 + x1 + 1] - nv;
            for (int q = qs; q < qe; q++) {
                uint4 C = hrec[q];
                unsigned long long ki = ((unsigned long long)C.y << 32) | C.x;
                if (ki <= kj) continue;            // lower rank / invalid / self
                float dx = __uint_as_float(C.z) - xj;
                float dy = __uint_as_float(C.w) - yj;
                if (dx * dx + dy * dy < D2_THRESH) {
                    if (cnt < NBR_CAP)
                        tmp[cnt] = rem ? (unsigned short)(0x8000u | hidx[q])
                                       : (unsigned short)q;
                    cnt++;
                }
            }
        }
        int i = hidx[p];
        if (cnt == 0) {
            PUBLISH(p, i, lr, 1u);
            EMIT(kj);
        } else {
            int w = atomicAdd(&s_wl, 1);
            wl[w] = (unsigned short)p;
            nbrcnt[w] = (cnt > NBR_CAP) ? (unsigned char)OVF : (unsigned char)cnt;
            #pragma unroll
            for (int k = 0; k < NBR_CAP; k++)
                if (k < cnt) nbr[w * NBR_CAP + k] = tmp[k];
        }
    }
    __syncthreads();
    const int nwl = s_wl;

    // ---- dataflow resolution: local via smem slice, cross-stripe via L2 ----
    for (int w = tid; w < nwl; w += NTHREADS) {
        int p = wl[w];
        int i = hidx[p];
        uint4 R = hrec[p];
        unsigned long long kj = ((unsigned long long)R.y << 32) | R.x;
        float xj = __uint_as_float(R.z), yj = __uint_as_float(R.w);
        int cy = min(63, max(0, (int)(yj * 0.125f)));
        int lr = cy - rbase;
        int c = nbrcnt[w];
        unsigned int res = 0;
        if (c != OVF) {
            while (res == 0) {
                bool sup = false, pend = false;
                #pragma unroll 1
                for (int k = 0; k < c; k++) {
                    unsigned short nb = nbr[w * NBR_CAP + k];
                    int st = (nb & 0x8000) ? vg[nb & 0x7FFF] : (int)vls[nb];
                    if (st == 1) { sup = true; break; }
                    if (st == 0) pend = true;
                }
                if (sup) res = 2;
                else if (!pend) res = 1;
            }
        } else {
            int cx = min(63, max(0, (int)(xj * 0.125f)));
            int x0 = max(cx - 1, 0), x1 = min(cx + 1, 63);
            while (res == 0) {
                bool sup = false, pend = false;
                #pragma unroll 1
                for (int rr = lr - 1; rr <= lr + 1 && !sup; rr++) {
                    bool rem = (rr == 0 || rr == 9);
                    int qs = cs[NBUCK + rr * 64 + x0] - nv;
                    int qe = cs[NBUCK + rr * 64 + x1 + 1] - nv;
                    for (int q = qs; q < qe; q++) {
                        uint4 C = hrec[q];
                        unsigned long long ki = ((unsigned long long)C.y << 32) | C.x;
                        if (ki <= kj) continue;
                        float dx = __uint_as_float(C.z) - xj;
                        float dy = __uint_as_float(C.w) - yj;
                        if (dx * dx + dy * dy < D2_THRESH) {
                            int st = rem ? vg[hidx[q]] : (int)vls[q];
                            if (st == 1) { sup = true; break; }
                            if (st == 0) pend = true;
                        }
                    }
                }
                if (sup) res = 2;
                else if (!pend) res = 1;
            }
        }
        PUBLISH(p, i, lr, res);
        if (res == 1) EMIT(kj);
    }
}

extern "C" void kernel_launch(void* const* d_in, const int* in_sizes, int n_in,
                              void* d_out, int out_size) {
    const float* logits = (const float*)d_in[0];   // [1,4096,3]
    const float* boxes  = (const float*)d_in[1];   // [1,4096,2]
    // d_in[2] = pred_gids (unused by reference)
    const float* ts     = (const float*)d_in[3];   // [1,2] = (w,h)
    float* out = (float*)d_out;                    // [1,4096,5]

    prep_kernel<<<2 * N_Q / NTHREADS, NTHREADS>>>(logits, boxes, ts, out);

    cudaFuncSetAttribute(resolve_kernel,
                         cudaFuncAttributeMaxDynamicSharedMemorySize, RES_SMEM);
    resolve_kernel<<<16, NTHREADS, RES_SMEM>>>(out);
}

// round 15
// speedup vs baseline: 1.8799x; 1.0017x over previous
#include <cuda_runtime.h>
#include <cstdint>

#define N_Q 4096
#define NTHREADS 1024
#define EVAL_PT_SCORE 0.05f
#define D2_THRESH 25.0f   // 5.0^2
#define NBR_CAP 6
#define OVF 255
#define BINCAP 1024
#define NBUCK 1024

// resolver smem: brec uint4[1024] | scs int[1025] | ccu int[1024] | hidx u16[1024]
//  | wl u16[1024] | rlist u16[1024] | nbr u16[6144] | lstat u8[1024] | nbrcnt u8[1024]
//  | warpsum int[32]
// builder smem:  bkey u64[4096] | cs int[1025] | ccu int[1024] | warpsum int[32]
#define SMEM_BYTES 45192

// -------- device scratch --------
__device__ uint4 g_binrec[2][8][BINCAP];        // (keylo,keyhi,x,y) per stripe bin
__device__ unsigned short g_binidx[2][8][BINCAP];
__device__ int g_bincnt[2][8];
__device__ unsigned long long g_key[2][N_Q];
__device__ int g_stat[2][N_Q];                  // 0 pending / 1 retained / 2 suppressed
__device__ unsigned short g_rank[2][N_Q];
__device__ int g_rankdone[2];

__device__ __forceinline__ int warp_incl_scan(int v) {
    int lane = threadIdx.x & 31;
    #pragma unroll
    for (int o = 1; o < 32; o <<= 1) {
        int n = __shfl_up_sync(0xffffffffu, v, o);
        if (lane >= o) v += n;
    }
    return v;
}

__device__ __forceinline__ unsigned long long mk_key(float s, int i) {
    bool valid = (s >= EVAL_PT_SCORE);
    unsigned int fb = __float_as_uint(s);
    return valid
        ? ((((unsigned long long)fb) << 32) | (unsigned int)(N_Q - 1 - i))
        : (unsigned long long)(unsigned int)(N_Q - 1 - i);
}

// ---------------- K1: prep (8 CTAs, 1 pt/thread) ----------------
__global__ void __launch_bounds__(NTHREADS)
prep_kernel(const float* __restrict__ logits,
            const float* __restrict__ boxes,
            const float* __restrict__ ts,
            float* __restrict__ out) {
    int t = blockIdx.x * NTHREADS + threadIdx.x;   // 0..8191
    if (t == 0) { g_rankdone[0] = 0; g_rankdone[1] = 0; }
    int cls = t >> 12;
    int j = t & (N_Q - 1);
    float l0 = logits[3 * j + 0];
    float l1 = logits[3 * j + 1];
    float l2 = logits[3 * j + 2];
    float m = fmaxf(l0, fmaxf(l1, l2));
    float e0 = __expf(l0 - m), e1 = __expf(l1 - m), e2 = __expf(l2 - m);
    float inv = __fdividef(1.0f, e0 + e1 + e2);
    float p0 = e0 * inv, p1 = e1 * inv, p2 = e2 * inv;
    float x = boxes[2 * j + 0] * ts[0];
    float y = boxes[2 * j + 1] * ts[1];
    float s = cls ? p1 : p0;
    unsigned long long key = mk_key(s, j);
    g_key[cls][j] = key;
    g_stat[cls][j] = (s >= EVAL_PT_SCORE) ? 0 : 2;

    int cy = min(63, max(0, (int)(y * 0.125f)));
    uint4 rec = make_uint4((unsigned int)key, (unsigned int)(key >> 32),
                           __float_as_uint(x), __float_as_uint(y));
    int b0 = cy >> 3, mrow = cy & 7;
    {
        int pos = atomicAdd(&g_bincnt[cls][b0], 1);
        if (pos < BINCAP) { g_binrec[cls][b0][pos] = rec; g_binidx[cls][b0][pos] = (unsigned short)j; }
    }
    if (mrow == 0 && b0 > 0) {
        int pos = atomicAdd(&g_bincnt[cls][b0 - 1], 1);
        if (pos < BINCAP) { g_binrec[cls][b0 - 1][pos] = rec; g_binidx[cls][b0 - 1][pos] = (unsigned short)j; }
    }
    if (mrow == 7 && b0 < 7) {
        int pos = atomicAdd(&g_bincnt[cls][b0 + 1], 1);
        if (pos < BINCAP) { g_binrec[cls][b0 + 1][pos] = rec; g_binidx[cls][b0 + 1][pos] = (unsigned short)j; }
    }

    if (cls == 0) {
        out[5 * j + 0] = 1.0f - p2;
        out[5 * j + 1] = x;
        out[5 * j + 2] = y;
        out[5 * j + 3] = 0.0f;
    } else {
        out[5 * j + 4] = 0.0f;
    }
}

// ---------------- K2: 16 stripe resolvers + 2 rank builders ----------------
__global__ void __launch_bounds__(NTHREADS, 1)
resolve_kernel(float* __restrict__ out) {
    const int tid = threadIdx.x;
    const int lane = tid & 31;
    const int wid = tid >> 5;
    extern __shared__ unsigned char sm[];

    if (blockIdx.x >= 16) {
        // ======== rank builder for class cls ========
        const int cls = blockIdx.x - 16;
        unsigned long long* bkey = (unsigned long long*)sm;        // [N_Q]
        int* cs  = (int*)(bkey + N_Q);                             // [NBUCK+1]
        int* ccu = cs + (NBUCK + 1);                               // [NBUCK]
        int* warpsum = ccu + NBUCK;                                // [32]

        cs[tid] = 0;
        if (tid == 0) cs[NBUCK] = 0;
        __syncthreads();

        unsigned long long k4[4];
        int b4[4];
        #pragma unroll
        for (int k = 0; k < 4; k++) {
            int j = k * NTHREADS + tid;
            unsigned long long key = g_key[cls][j];
            k4[k] = key;
            if (key >> 32) {
                float s = __uint_as_float((unsigned int)(key >> 32));
                b4[k] = min(NBUCK - 1, (int)(s * (float)NBUCK));
                atomicAdd(&cs[b4[k]], 1);
            } else b4[k] = 0;
        }
        __syncthreads();
        {
            int v = cs[tid];
            int iv = warp_incl_scan(v);
            if (lane == 31) warpsum[wid] = iv;
            __syncthreads();
            if (wid == 0) warpsum[lane] = warp_incl_scan(warpsum[lane]);
            __syncthreads();
            int ex = iv - v + (wid ? warpsum[wid - 1] : 0);
            cs[tid] = ex; ccu[tid] = ex;
            if (tid == NTHREADS - 1) cs[NBUCK] = ex + v;
        }
        __syncthreads();
        const int nv = cs[NBUCK];
        #pragma unroll
        for (int k = 0; k < 4; k++) {
            if (k4[k] >> 32) {
                int bp = atomicAdd(&ccu[b4[k]], 1);
                bkey[bp] = k4[k];
            }
        }
        __syncthreads();
        #pragma unroll
        for (int k = 0; k < 4; k++) {
            if (!(k4[k] >> 32)) continue;
            int b = b4[k];
            int r = nv - cs[b + 1];
            int e = cs[b + 1];
            for (int q = cs[b]; q < e; q++)
                if (bkey[q] > k4[k]) r++;
            g_rank[cls][k * NTHREADS + tid] = (unsigned short)r;
        }
        __syncthreads();
        __threadfence();
        if (tid == 0) g_rankdone[cls] = 1;
        return;
    }

    // ======== stripe resolver ========
    const int rank = blockIdx.x & 7;
    const int cls = blockIdx.x >> 3;
    const int rbase = 8 * rank - 1;          // local row 0 = cell row rbase

    uint4* brec = (uint4*)sm;                                     // [1024]
    int* scs = (int*)(brec + BINCAP);                             // [1025]
    int* ccu = scs + 1025;                                        // [1024]
    unsigned short* hidx  = (unsigned short*)(ccu + 1024);        // [1024]
    unsigned short* wl    = hidx + BINCAP;                        // [1024]
    unsigned short* rlist = wl + BINCAP;                          // [1024]
    unsigned short* nbr   = rlist + BINCAP;                       // [1024*6]
    unsigned char* lstat  = (unsigned char*)(nbr + BINCAP * NBR_CAP); // [1024]
    unsigned char* nbrcnt = lstat + BINCAP;                       // [1024]
    int* warpsum = (int*)(nbrcnt + BINCAP);                       // [32]
    volatile unsigned char* vls = (volatile unsigned char*)lstat;
    volatile int* vg = (volatile int*)g_stat[cls];
    __shared__ int s_wl, s_nr;

    const int nbin = min(g_bincnt[cls][rank], BINCAP);

    scs[tid] = 0;
    if (tid == 0) { scs[1024] = 0; s_wl = 0; s_nr = 0; }
    __syncthreads();

    // pass 1: histogram over local cells (lr = cy - rbase in [0,9])
    for (int p = tid; p < nbin; p += NTHREADS) {
        uint4 R = g_binrec[cls][rank][p];
        int cx = min(63, max(0, (int)(__uint_as_float(R.z) * 0.125f)));
        int cy = min(63, max(0, (int)(__uint_as_float(R.w) * 0.125f)));
        atomicAdd(&scs[(cy - rbase) * 64 + cx], 1);
    }
    __syncthreads();
    // scan 1024 (cells 0..639 live; rest zero)
    {
        int v = scs[tid];
        int iv = warp_incl_scan(v);
        if (lane == 31) warpsum[wid] = iv;
        __syncthreads();
        if (wid == 0) warpsum[lane] = warp_incl_scan(warpsum[lane]);
        __syncthreads();
        int ex = iv - v + (wid ? warpsum[wid - 1] : 0);
        scs[tid] = ex; ccu[tid] = ex;
        if (tid == NTHREADS - 1) scs[1024] = ex + v;
    }
    __syncthreads();
    // pass 2: scatter into cell order (re-read bin from L2)
    for (int p = tid; p < nbin; p += NTHREADS) {
        uint4 R = g_binrec[cls][rank][p];
        int cx = min(63, max(0, (int)(__uint_as_float(R.z) * 0.125f)));
        int cy = min(63, max(0, (int)(__uint_as_float(R.w) * 0.125f)));
        int pos = atomicAdd(&ccu[(cy - rbase) * 64 + cx], 1);
        brec[pos] = R;
        hidx[pos] = g_binidx[cls][rank][p];
        lstat[pos] = R.y ? (unsigned char)0 : (unsigned char)2;
    }
    __syncthreads();

    const int pstart = scs[64];         // owned rows: lr 1..8 => cells [64,576)
    const int pend   = scs[576];

    #define PUBLISH(p, idx, cy, v) do {                                       \
        vls[p] = (unsigned char)(v);                                          \
        int m_ = (cy) & 7;                                                    \
        if ((m_ == 0 && rank > 0) || (m_ == 7 && rank < 7))                   \
            vg[idx] = (int)(v);                                               \
    } while (0)

    // ---- edge build for owned records ----
    for (int p = pstart + tid; p < pend; p += NTHREADS) {
        uint4 R = brec[p];
        if (R.y == 0) continue;                    // invalid
        unsigned long long kj = ((unsigned long long)R.y << 32) | R.x;
        float xj = __uint_as_float(R.z), yj = __uint_as_float(R.w);
        int cx = min(63, max(0, (int)(xj * 0.125f)));
        int cy = min(63, max(0, (int)(yj * 0.125f)));
        int lr = cy - rbase;                       // 1..8
        int x0 = max(cx - 1, 0), x1 = min(cx + 1, 63);
        unsigned short tmp[NBR_CAP];
        int cnt = 0;
        for (int rr = lr - 1; rr <= lr + 1; rr++) {
            int qs = scs[rr * 64 + x0];
            int qe = scs[rr * 64 + x1 + 1];
            for (int q = qs; q < qe; q++) {
                uint4 C = brec[q];
                unsigned long long ki = ((unsigned long long)C.y << 32) | C.x;
                if (ki <= kj) continue;            // lower rank / invalid / self
                float dx = __uint_as_float(C.z) - xj;
                float dy = __uint_as_float(C.w) - yj;
                if (dx * dx + dy * dy < D2_THRESH) {
                    if (cnt < NBR_CAP) {
                        bool rem = (q < pstart) || (q >= pend);
                        tmp[cnt] = rem ? (unsigned short)(0x8000u | hidx[q])
                                       : (unsigned short)q;
                    }
                    cnt++;
                }
            }
        }
        int i = hidx[p];
        if (cnt == 0) {
            PUBLISH(p, i, cy, 1u);
            rlist[atomicAdd(&s_nr, 1)] = (unsigned short)p;
        } else {
            int w = atomicAdd(&s_wl, 1);
            wl[w] = (unsigned short)p;
            nbrcnt[w] = (cnt > NBR_CAP) ? (unsigned char)OVF : (unsigned char)cnt;
            #pragma unroll
            for (int k = 0; k < NBR_CAP; k++)
                if (k < cnt) nbr[w * NBR_CAP + k] = tmp[k];
        }
    }
    __syncthreads();
    const int nwl = s_wl;

    // ---- dataflow resolve: local smem / remote L2 ----
    for (int w = tid; w < nwl; w += NTHREADS) {
        int p = wl[w];
        int i = hidx[p];
        uint4 R = brec[p];
        unsigned long long kj = ((unsigned long long)R.y << 32) | R.x;
        float xj = __uint_as_float(R.z), yj = __uint_as_float(R.w);
        int cy = min(63, max(0, (int)(yj * 0.125f)));
        int c = nbrcnt[w];
        unsigned int res = 0;
        if (c != OVF) {
            while (res == 0) {
                bool sup = false, pend2 = false;
                #pragma unroll 1
                for (int k = 0; k < c; k++) {
                    unsigned short nb = nbr[w * NBR_CAP + k];
                    int st = (nb & 0x8000) ? vg[nb & 0x7FFF] : (int)vls[nb];
                    if (st == 1) { sup = true; break; }
                    if (st == 0) pend2 = true;
                }
                if (sup) res = 2;
                else if (!pend2) res = 1;
            }
        } else {
            int cx = min(63, max(0, (int)(xj * 0.125f)));
            int lr = cy - rbase;
            int x0 = max(cx - 1, 0), x1 = min(cx + 1, 63);
            while (res == 0) {
                bool sup = false, pend2 = false;
                for (int rr = lr - 1; rr <= lr + 1 && !sup; rr++) {
                    int qs = scs[rr * 64 + x0];
                    int qe = scs[rr * 64 + x1 + 1];
                    for (int q = qs; q < qe; q++) {
                        uint4 C = brec[q];
                        unsigned long long ki = ((unsigned long long)C.y << 32) | C.x;
                        if (ki <= kj) continue;
                        float dx = __uint_as_float(C.z) - xj;
                        float dy = __uint_as_float(C.w) - yj;
                        if (dx * dx + dy * dy < D2_THRESH) {
                            bool rem2 = (q < pstart) || (q >= pend);
                            int st = rem2 ? vg[hidx[q]] : (int)vls[q];
                            if (st == 1) { sup = true; break; }
                            if (st == 0) pend2 = true;
                        }
                    }
                }
                if (sup) res = 2;
                else if (!pend2) res = 1;
            }
        }
        PUBLISH(p, i, cy, res);
        if (res == 1) rlist[atomicAdd(&s_nr, 1)] = (unsigned short)p;
    }
    __syncthreads();

    // ---- emit retained after rank table is ready ----
    const int nret = s_nr;
    if (tid == 0) {
        volatile int* vf = (volatile int*)&g_rankdone[cls];
        while (*vf == 0) { }
    }
    __syncthreads();
    for (int t = tid; t < nret; t += NTHREADS) {
        int p = rlist[t];
        int idx = hidx[p];
        unsigned int keyhi = brec[p].y;
        out[5 * (int)g_rank[cls][idx] + 3 + cls] = __uint_as_float(keyhi);
    }
    if (tid == 0) g_bincnt[cls][rank] = 0;   // reset cursor for next replay
}

extern "C" void kernel_launch(void* const* d_in, const int* in_sizes, int n_in,
                              void* d_out, int out_size) {
    const float* logits = (const float*)d_in[0];   // [1,4096,3]
    const float* boxes  = (const float*)d_in[1];   // [1,4096,2]
    // d_in[2] = pred_gids (unused by reference)
    const float* ts     = (const float*)d_in[3];   // [1,2] = (w,h)
    float* out = (float*)d_out;                    // [1,4096,5]

    prep_kernel<<<2 * N_Q / NTHREADS, NTHREADS>>>(logits, boxes, ts, out);

    cudaFuncSetAttribute(resolve_kernel,
                         cudaFuncAttributeMaxDynamicSharedMemorySize, SMEM_BYTES);
    resolve_kernel<<<18, NTHREADS, SMEM_BYTES>>>(out);
}